// round 3
// baseline (speedup 1.0000x reference)
#include <cuda_runtime.h>
#include <cuda_fp16.h>

#define BATCH 64
#define MM 512
#define NN 512
#define DH 64
#define NDIAG (MM + NN - 1)   /* 1023 */
#define BIGF 1e10f
#define SCALE_EX2 14.4269504088896f   /* (1/gamma) * log2(e), gamma = 0.1 */
#define GLN2 0.0693147180559945f      /* gamma * ln(2) */

// Diagonal-major distance matrix, fp16: Ddiag[b][(i+j)][i] = D[b][i][j]
__device__ __half g_Ddiag[(size_t)BATCH * NDIAG * MM];
__device__ float g_perbatch[BATCH];

__device__ __forceinline__ float ex2f(float x) {
    float r; asm("ex2.approx.ftz.f32 %0, %1;" : "=f"(r) : "f"(x)); return r;
}
__device__ __forceinline__ float lg2f(float x) {
    float r; asm("lg2.approx.ftz.f32 %0, %1;" : "=f"(r) : "f"(x)); return r;
}

// ---------------------------------------------------------------------------
// Kernel 1: pairwise squared L2 -> diagonal-major fp16.
// Grid (8,8,64), 256 threads, 4x4 microtile. Norms hoisted out of k-loop.
// ---------------------------------------------------------------------------
__global__ __launch_bounds__(256) void pairwise_diag_kernel(
    const float* __restrict__ x, const float* __restrict__ y)
{
    __shared__ float xs[64][65];
    __shared__ float ys[64][65];
    __shared__ float Cs[64][66];
    __shared__ float xn[64], yn[64];

    int b  = blockIdx.z;
    int i0 = blockIdx.y * 64;
    int j0 = blockIdx.x * 64;
    int tid = threadIdx.x;

    const float* xb = x + ((size_t)b * MM + i0) * DH;
    const float* yb = y + ((size_t)b * NN + j0) * DH;

    for (int e = tid; e < 64 * 64; e += 256) {
        int r = e >> 6, c = e & 63;
        xs[r][c] = xb[r * DH + c];
        ys[r][c] = yb[r * DH + c];
    }
    __syncthreads();

    // Precompute row norms (threads 0-63: x, 64-127: y)
    if (tid < 64) {
        float s = 0.0f;
        #pragma unroll 8
        for (int k = 0; k < DH; k++) { float v = xs[tid][k]; s += v * v; }
        xn[tid] = s;
    } else if (tid < 128) {
        int j = tid - 64;
        float s = 0.0f;
        #pragma unroll 8
        for (int k = 0; k < DH; k++) { float v = ys[j][k]; s += v * v; }
        yn[j] = s;
    }
    __syncthreads();

    int ty = tid >> 4, tx = tid & 15;
    float acc[4][4] = {};

    #pragma unroll 4
    for (int k = 0; k < DH; k++) {
        float a0 = xs[ty * 4 + 0][k], a1 = xs[ty * 4 + 1][k];
        float a2 = xs[ty * 4 + 2][k], a3 = xs[ty * 4 + 3][k];
        float b0 = ys[tx * 4 + 0][k], b1 = ys[tx * 4 + 1][k];
        float b2 = ys[tx * 4 + 2][k], b3 = ys[tx * 4 + 3][k];
        acc[0][0] += a0 * b0; acc[0][1] += a0 * b1; acc[0][2] += a0 * b2; acc[0][3] += a0 * b3;
        acc[1][0] += a1 * b0; acc[1][1] += a1 * b1; acc[1][2] += a1 * b2; acc[1][3] += a1 * b3;
        acc[2][0] += a2 * b0; acc[2][1] += a2 * b1; acc[2][2] += a2 * b2; acc[2][3] += a2 * b3;
        acc[3][0] += a3 * b0; acc[3][1] += a3 * b1; acc[3][2] += a3 * b2; acc[3][3] += a3 * b3;
    }

    #pragma unroll
    for (int r = 0; r < 4; r++)
        #pragma unroll
        for (int c = 0; c < 4; c++)
            Cs[ty * 4 + r][tx * 4 + c] =
                fmaxf(xn[ty * 4 + r] + yn[tx * 4 + c] - 2.0f * acc[r][c], 0.0f);
    __syncthreads();

    // Emit tile anti-diagonals (contiguous in i -> coalesced fp16 stores).
    __half* out = g_Ddiag + (size_t)b * NDIAG * MM;
    int warp = tid >> 5, lane = tid & 31;
    for (int s = warp; s < 127; s += 8) {
        int lo = (s > 63) ? (s - 63) : 0;
        int hi = (s < 63) ? s : 63;
        for (int li = lo + lane; li <= hi; li += 32) {
            out[(size_t)(i0 + j0 + s) * MM + i0 + li] = __float2half_rn(Cs[li][s - li]);
        }
    }
}

// ---------------------------------------------------------------------------
// Kernel 2: soft-DTW wavefront. One CTA per batch, 128 threads, 4 rows/thread
// in registers. Per global anti-diagonal d each thread computes 4 independent
// cells; boundary row passes via shfl_up (in-warp) + 2-slot smem (cross-warp).
// ---------------------------------------------------------------------------
__device__ __forceinline__ float cellv(float dg, float up, float lf,
                                       float D, int j)
{
    // softmin_gamma(dg, up, lf): sort3, exploit exp(0)=1 -> 3 MUFU total
    float mn1 = fminf(dg, up), mx1 = fmaxf(dg, up);
    float m   = fminf(mn1, lf);
    float mid = fmaxf(fminf(mx1, lf), mn1);
    float mx  = fmaxf(mx1, lf);
    float mc  = m * SCALE_EX2;
    float e1  = ex2f(fmaf(mid, -SCALE_EX2, mc));
    float e2  = ex2f(fmaf(mx,  -SCALE_EX2, mc));
    float sum = 1.0f + e1 + e2;
    float r   = fmaf(-GLN2, lg2f(sum), m) + D;
    return ((unsigned)j <= (unsigned)(NN - 1)) ? r : BIGF;
}

__global__ __launch_bounds__(128) void dtw_kernel()
{
    __shared__ float sm_c3[4][2];   // [producer warp][step parity]

    int b = blockIdx.x;
    int t = threadIdx.x;
    int w = t >> 5, lane = t & 31;

    if (t < 8) sm_c3[t >> 1][t & 1] = BIGF;
    __syncthreads();

    const __half* Db = g_Ddiag + (size_t)b * NDIAG * MM + 4 * t;

    float p1_0 = BIGF, p1_1 = BIGF, p1_2 = BIGF, p1_3 = BIGF;   // d-1 values
    float p2_0 = BIGF, p2_1 = BIGF, p2_2 = BIGF;                 // d-2 values
    float nb2 = (t == 0) ? 0.0f : BIGF;  // neighbor c3 at d-2 (C(-1,-1)=0 seed)

    uint2 dv0 = {0,0}, dv1 = {0,0}, dv2 = {0,0};
    const int wlo = w * 128;
    const int whi = wlo + 638;
    const int i0 = 4 * t;

    for (int d = 0; d < NDIAG; d++) {
        if (d >= wlo && d <= whi) {           // warp-uniform activity window
            if (d == wlo) {                    // prime 3-deep prefetch
                dv0 = *(const uint2*)(Db + (size_t)d * MM);
                if (d + 1 < NDIAG) dv1 = *(const uint2*)(Db + (size_t)(d + 1) * MM);
                if (d + 2 < NDIAG) dv2 = *(const uint2*)(Db + (size_t)(d + 2) * MM);
            }

            float nb1 = __shfl_up_sync(0xffffffffu, p1_3, 1);  // neighbor c3 @ d-1
            if (lane == 0)
                nb1 = (w == 0) ? BIGF : sm_c3[w - 1][(d & 1) ^ 1];

            float2 dlo = __half22float2(*(const __half2*)&dv0.x);
            float2 dhi = __half22float2(*(const __half2*)&dv0.y);

            float c0 = cellv(nb2,  nb1,  p1_0, dlo.x, d - i0);
            float c1 = cellv(p2_0, p1_0, p1_1, dlo.y, d - i0 - 1);
            float c2 = cellv(p2_1, p1_1, p1_2, dhi.x, d - i0 - 2);
            float c3 = cellv(p2_2, p1_2, p1_3, dhi.y, d - i0 - 3);

            if (lane == 31) sm_c3[w][d & 1] = c3;

            nb2 = nb1;
            p2_0 = p1_0; p2_1 = p1_1; p2_2 = p1_2;
            p1_0 = c0;   p1_1 = c1;   p1_2 = c2;   p1_3 = c3;

            dv0 = dv1; dv1 = dv2;
            int dn = d + 3;
            if (dn <= whi) dv2 = *(const uint2*)(Db + (size_t)dn * MM);
        }
        __syncthreads();
    }

    if (t == 127) g_perbatch[b] = p1_3;   // C(511,511)
}

// ---------------------------------------------------------------------------
// Kernel 3: deterministic mean over batches.
// ---------------------------------------------------------------------------
__global__ void reduce_kernel(float* __restrict__ out)
{
    __shared__ float s[BATCH];
    s[threadIdx.x] = g_perbatch[threadIdx.x];
    __syncthreads();
    if (threadIdx.x == 0) {
        float acc = 0.0f;
        for (int i = 0; i < BATCH; i++) acc += s[i];
        out[0] = acc * (1.0f / BATCH);
    }
}

extern "C" void kernel_launch(void* const* d_in, const int* in_sizes, int n_in,
                              void* d_out, int out_size)
{
    const float* x = (const float*)d_in[0];
    const float* y = (const float*)d_in[1];
    float* out = (float*)d_out;

    dim3 g1(NN / 64, MM / 64, BATCH);
    pairwise_diag_kernel<<<g1, 256>>>(x, y);
    dtw_kernel<<<BATCH, 128>>>();
    reduce_kernel<<<1, BATCH>>>(out);
}

// round 4
// speedup vs baseline: 1.3110x; 1.3110x over previous
#include <cuda_runtime.h>
#include <cuda_fp16.h>

#define BATCH 64
#define MM 512
#define NN 512
#define DH 64
#define NDIAG (MM + NN - 1)   /* 1023 */
#define BIGF 1e10f
#define SCALE_EX2 14.4269504088896f   /* (1/gamma) * log2(e), gamma = 0.1 */
#define GLN2 0.0693147180559945f      /* gamma * ln(2) */
#define POISON 0x7FBFFFFFu            /* NaN pattern never produced by the DP */

// Diagonal-major distance matrix, fp16: Ddiag[b][(i+j)][i] = D[b][i][j]
__device__ __half g_Ddiag[(size_t)BATCH * NDIAG * MM];
__device__ float g_perbatch[BATCH];

__device__ __forceinline__ float ex2f(float x) {
    float r; asm("ex2.approx.ftz.f32 %0, %1;" : "=f"(r) : "f"(x)); return r;
}
__device__ __forceinline__ float lg2f(float x) {
    float r; asm("lg2.approx.ftz.f32 %0, %1;" : "=f"(r) : "f"(x)); return r;
}

// ---------------------------------------------------------------------------
// Kernel 1: pairwise squared L2 -> diagonal-major fp16.
// Grid (8,8,64), 256 threads, 4x4 microtile, float4 smem loads (FMA-bound).
// ---------------------------------------------------------------------------
#define XS(r,c) pool[(r) * 68 + (c)]
#define YS(r,c) pool[4352 + (r) * 68 + (c)]
#define CS(r,c) pool[(r) * 66 + (c)]   /* overlays XS region after k-loop */

__global__ __launch_bounds__(256) void pairwise_diag_kernel(
    const float* __restrict__ x, const float* __restrict__ y)
{
    __shared__ float pool[2 * 64 * 68];   // 34.8 KB
    __shared__ float xn[64], yn[64];

    int b  = blockIdx.z;
    int i0 = blockIdx.y * 64;
    int j0 = blockIdx.x * 64;
    int tid = threadIdx.x;

    const float* xb = x + ((size_t)b * MM + i0) * DH;
    const float* yb = y + ((size_t)b * NN + j0) * DH;

    // Vectorized tile load: 1024 float4 per tensor, 4 per thread.
    #pragma unroll
    for (int e = tid; e < 1024; e += 256) {
        int r = e >> 4, c = (e & 15) * 4;
        *(float4*)&XS(r, c) = *(const float4*)&xb[r * DH + c];
        *(float4*)&YS(r, c) = *(const float4*)&yb[r * DH + c];
    }
    __syncthreads();

    // Row norms (threads 0-63: x, 64-127: y), float4 reads.
    if (tid < 128) {
        int r = tid & 63;
        const float* row = (tid < 64) ? &XS(r, 0) : &YS(r, 0);
        float s = 0.0f;
        #pragma unroll
        for (int k = 0; k < DH; k += 4) {
            float4 v = *(const float4*)&row[k];
            s += v.x * v.x + v.y * v.y + v.z * v.z + v.w * v.w;
        }
        if (tid < 64) xn[r] = s; else yn[r] = s;
    }
    __syncthreads();

    int ty4 = (tid >> 4) * 4, tx4 = (tid & 15) * 4;
    float acc[4][4] = {};

    #pragma unroll 2
    for (int k = 0; k < DH; k += 4) {
        float4 av[4], bv[4];
        #pragma unroll
        for (int r = 0; r < 4; r++) av[r] = *(const float4*)&XS(ty4 + r, k);
        #pragma unroll
        for (int c = 0; c < 4; c++) bv[c] = *(const float4*)&YS(tx4 + c, k);
        const float* af = (const float*)av;
        const float* bf = (const float*)bv;
        #pragma unroll
        for (int kk = 0; kk < 4; kk++)
            #pragma unroll
            for (int r = 0; r < 4; r++)
                #pragma unroll
                for (int c = 0; c < 4; c++)
                    acc[r][c] += af[r * 4 + kk] * bf[c * 4 + kk];
    }
    __syncthreads();   // done reading XS before CS overlays it

    #pragma unroll
    for (int r = 0; r < 4; r++)
        #pragma unroll
        for (int c = 0; c < 4; c++)
            CS(ty4 + r, tx4 + c) =
                fmaxf(xn[ty4 + r] + yn[tx4 + c] - 2.0f * acc[r][c], 0.0f);
    __syncthreads();

    // Emit tile anti-diagonals, half2-vectorized, 32-bit addressing.
    // Global element index for (li, s-li): (i0+j0+s)*512 + i0 + li (contiguous in li).
    __half* outb = g_Ddiag + (size_t)b * (NDIAG * MM);
    int warp = tid >> 5, lane = tid & 31;
    for (int s = warp; s < 127; s += 8) {
        int lo = (s > 63) ? (s - 63) : 0;
        int hi = (s < 63) ? s : 63;
        __half* rp = outb + (unsigned)(i0 + j0 + s) * 512u + (unsigned)i0;
        if (lo & 1) {                       // unaligned head
            if (lane == 0) rp[lo] = __float2half_rn(CS(lo, s - lo));
            lo++;
        }
        int li = lo + 2 * lane;
        if (li + 1 <= hi) {                 // aligned pairs (max 64 elems -> 1 iter)
            __half2 v = __halves2half2(__float2half_rn(CS(li, s - li)),
                                       __float2half_rn(CS(li + 1, s - li - 1)));
            *(__half2*)(rp + li) = v;
        }
        if (((hi - lo) & 1) == 0) {         // unpaired tail
            if (lane == 0) rp[hi] = __float2half_rn(CS(hi, s - hi));
        }
    }
}

// ---------------------------------------------------------------------------
// Kernel 2: soft-DTW, barrier-free warp-pipelined wavefront.
// One CTA per batch, 128 threads, 4 rows/thread in registers. Each warp loops
// only over its 639 active diagonals. Cross-warp boundary value flows through
// a full-length smem array (volatile 4B store / poll), warps self-pipeline.
// ---------------------------------------------------------------------------
__device__ __forceinline__ float cellv(float dg, float up, float lf,
                                       float D, int j)
{
    // softmin_gamma(dg, up, lf): sort3, exp(0)=1 -> 2x ex2 + 1x lg2
    float mn1 = fminf(dg, up), mx1 = fmaxf(dg, up);
    float m   = fminf(mn1, lf);
    float mid = fmaxf(fminf(mx1, lf), mn1);
    float mx  = fmaxf(mx1, lf);
    float mc  = m * SCALE_EX2;
    float e1  = ex2f(fmaf(mid, -SCALE_EX2, mc));
    float e2  = ex2f(fmaf(mx,  -SCALE_EX2, mc));
    float sum = 1.0f + e1 + e2;
    float r   = fmaf(-GLN2, lg2f(sum), m) + D;
    return ((unsigned)j <= (unsigned)(NN - 1)) ? r : BIGF;
}

__global__ __launch_bounds__(128) void dtw_kernel()
{
    __shared__ unsigned sm_bound[3][NDIAG];   // boundary c3 of warps 0..2, 12.3KB

    int b = blockIdx.x;
    int t = threadIdx.x;
    int w = t >> 5, lane = t & 31;

    for (int e = t; e < 3 * NDIAG; e += 128)
        ((unsigned*)sm_bound)[e] = POISON;
    __syncthreads();   // only barrier in the kernel

    const __half* Db = g_Ddiag + (size_t)b * (NDIAG * MM) + 4 * t;
    const int i0   = 4 * t;
    const int wlo  = w * 128;
    const int whi  = wlo + 638;
    const int pwhi = wlo + 510;   // producer warp's last active diagonal (w>0)

    float p1_0 = BIGF, p1_1 = BIGF, p1_2 = BIGF, p1_3 = BIGF;  // d-1 row
    float p2_0 = BIGF, p2_1 = BIGF, p2_2 = BIGF;               // d-2 row
    float nb2 = (t == 0) ? 0.0f : BIGF;   // neighbor c3 @ d-2 (C(-1,-1)=0 seed)

    // 3-deep D prefetch (uint2 = 4 half)
    uint2 dv0 = *(const uint2*)(Db + (size_t)wlo * MM);
    uint2 dv1 = *(const uint2*)(Db + (size_t)(wlo + 1) * MM);
    uint2 dv2 = *(const uint2*)(Db + (size_t)(wlo + 2) * MM);

    volatile unsigned* prod = (w > 0) ? &sm_bound[w - 1][0] : 0;

    for (int d = wlo; d <= whi; d++) {
        float nb1 = __shfl_up_sync(0xffffffffu, p1_3, 1);  // neighbor c3 @ d-1
        if (lane == 0) {
            if (w == 0 || d - 1 > pwhi) {
                nb1 = BIGF;
            } else {
                unsigned v = prod[d - 1];
                while (v == POISON) v = prod[d - 1];   // producer runs ~128 ahead
                nb1 = __uint_as_float(v);
            }
        }

        float2 dlo = __half22float2(*(const __half2*)&dv0.x);
        float2 dhi = __half22float2(*(const __half2*)&dv0.y);

        float c0 = cellv(nb2,  nb1,  p1_0, dlo.x, d - i0);
        float c1 = cellv(p2_0, p1_0, p1_1, dlo.y, d - i0 - 1);
        float c2 = cellv(p2_1, p1_1, p1_2, dhi.x, d - i0 - 2);
        float c3 = cellv(p2_2, p1_2, p1_3, dhi.y, d - i0 - 3);

        if (w < 3 && lane == 31)
            ((volatile unsigned*)&sm_bound[w][d])[0] = __float_as_uint(c3);

        nb2 = nb1;
        p2_0 = p1_0; p2_1 = p1_1; p2_2 = p1_2;
        p1_0 = c0;   p1_1 = c1;   p1_2 = c2;   p1_3 = c3;

        dv0 = dv1; dv1 = dv2;
        if (d + 3 <= whi) dv2 = *(const uint2*)(Db + (size_t)(d + 3) * MM);
    }

    if (t == 127) g_perbatch[b] = p1_3;   // C(511,511)
}

// ---------------------------------------------------------------------------
// Kernel 3: deterministic mean over batches.
// ---------------------------------------------------------------------------
__global__ void reduce_kernel(float* __restrict__ out)
{
    __shared__ float s[BATCH];
    s[threadIdx.x] = g_perbatch[threadIdx.x];
    __syncthreads();
    if (threadIdx.x == 0) {
        float acc = 0.0f;
        for (int i = 0; i < BATCH; i++) acc += s[i];
        out[0] = acc * (1.0f / BATCH);
    }
}

extern "C" void kernel_launch(void* const* d_in, const int* in_sizes, int n_in,
                              void* d_out, int out_size)
{
    const float* x = (const float*)d_in[0];
    const float* y = (const float*)d_in[1];
    float* out = (float*)d_out;

    dim3 g1(NN / 64, MM / 64, BATCH);
    pairwise_diag_kernel<<<g1, 256>>>(x, y);
    dtw_kernel<<<BATCH, 128>>>();
    reduce_kernel<<<1, BATCH>>>(out);
}

// round 8
// speedup vs baseline: 2.5875x; 1.9737x over previous
#include <cuda_runtime.h>
#include <cuda_fp16.h>

#define BATCH 64
#define MM 512
#define NN 512
#define DH 64
#define NDIAG (MM + NN - 1)   /* 1023 */
#define BIGF 1e10f
#define SCALE_EX2 14.4269504088896f   /* (1/gamma) * log2(e), gamma = 0.1 */
#define GLN2 0.0693147180559945f      /* gamma * ln(2) */
#define POISON 0x7FBFFFFFu            /* NaN pattern never produced by the DP */

// Diagonal-major distance matrix, fp16: Ddiag[b][(i+j)][i] = D[b][i][j]
__device__ __half g_Ddiag[(size_t)BATCH * NDIAG * MM];
__device__ float g_perbatch[BATCH];

__device__ __forceinline__ float ex2f(float x) {
    float r; asm("ex2.approx.ftz.f32 %0, %1;" : "=f"(r) : "f"(x)); return r;
}
__device__ __forceinline__ float lg2f(float x) {
    float r; asm("lg2.approx.ftz.f32 %0, %1;" : "=f"(r) : "f"(x)); return r;
}
__device__ __forceinline__ unsigned long long pk2(float lo, float hi) {
    unsigned long long p;
    asm("mov.b64 %0, {%1, %2};" : "=l"(p) : "f"(lo), "f"(hi));
    return p;
}
__device__ __forceinline__ void fma2(unsigned long long& acc,
                                     unsigned long long a, unsigned long long b) {
    asm("fma.rn.f32x2 %0, %1, %2, %0;" : "+l"(acc) : "l"(a), "l"(b));
}
__device__ __forceinline__ void upk2(unsigned long long p, float& lo, float& hi) {
    asm("mov.b64 {%0, %1}, %2;" : "=f"(lo), "=f"(hi) : "l"(p));
}

// ---------------------------------------------------------------------------
// Kernel 1: pairwise squared L2 -> diagonal-major fp16.
// Grid (8,8,64), 256 threads. 4x4 microtile with INTERLEAVED columns
// (thread covers cols tx+16c -> conflict-free scalar LDS), stride-65 smem,
// hoisted norms, packed f32x2 FMA (SASS FFMA2).
// ---------------------------------------------------------------------------
__global__ __launch_bounds__(256) void pairwise_diag_kernel(
    const float* __restrict__ x, const float* __restrict__ y)
{
    __shared__ float xs[64][65];
    __shared__ float ys[64][65];
    __shared__ float Cs[64][66];
    __shared__ float xn[64], yn[64];

    int b  = blockIdx.z;
    int i0 = blockIdx.y * 64;
    int j0 = blockIdx.x * 64;
    int tid = threadIdx.x;

    const float* xb = x + ((size_t)b * MM + i0) * DH;
    const float* yb = y + ((size_t)b * NN + j0) * DH;

    // Coalesced tile load (consecutive threads -> consecutive k), float4.
    #pragma unroll
    for (int e = tid; e < 1024; e += 256) {
        int r = e >> 4, c = (e & 15) * 4;
        float4 vx = *(const float4*)&xb[r * DH + c];
        float4 vy = *(const float4*)&yb[r * DH + c];
        xs[r][c] = vx.x; xs[r][c+1] = vx.y; xs[r][c+2] = vx.z; xs[r][c+3] = vx.w;
        ys[r][c] = vy.x; ys[r][c+1] = vy.y; ys[r][c+2] = vy.z; ys[r][c+3] = vy.w;
    }
    __syncthreads();

    // Row norms (threads 0-63: x, 64-127: y).
    if (tid < 128) {
        int r = tid & 63;
        const float* row = (tid < 64) ? &xs[r][0] : &ys[r][0];
        float s = 0.0f;
        #pragma unroll 8
        for (int k = 0; k < DH; k++) { float v = row[k]; s += v * v; }
        if (tid < 64) xn[r] = s; else yn[r] = s;
    }
    __syncthreads();

    int ty4 = (tid >> 4) * 4;    // rows ty4..ty4+3 (contiguous)
    int tx  = tid & 15;          // cols tx, tx+16, tx+32, tx+48 (interleaved)

    unsigned long long acc2[4][2] = {{0ull,0ull},{0ull,0ull},{0ull,0ull},{0ull,0ull}};

    #pragma unroll 4
    for (int k = 0; k < DH; k++) {
        float b0 = ys[tx     ][k];
        float b1 = ys[tx + 16][k];
        float b2 = ys[tx + 32][k];
        float b3 = ys[tx + 48][k];
        unsigned long long bp0 = pk2(b0, b1);
        unsigned long long bp1 = pk2(b2, b3);
        #pragma unroll
        for (int r = 0; r < 4; r++) {
            float a = xs[ty4 + r][k];
            unsigned long long ap = pk2(a, a);
            fma2(acc2[r][0], ap, bp0);
            fma2(acc2[r][1], ap, bp1);
        }
    }

    #pragma unroll
    for (int r = 0; r < 4; r++) {
        float xnr = xn[ty4 + r];
        #pragma unroll
        for (int cp = 0; cp < 2; cp++) {
            float v0, v1;
            upk2(acc2[r][cp], v0, v1);
            int c0 = tx + 16 * (2 * cp);
            int c1 = tx + 16 * (2 * cp + 1);
            Cs[ty4 + r][c0] = fmaxf(xnr + yn[c0] - 2.0f * v0, 0.0f);
            Cs[ty4 + r][c1] = fmaxf(xnr + yn[c1] - 2.0f * v1, 0.0f);
        }
    }
    __syncthreads();

    // Emit tile anti-diagonals: diag s elements (li, s-li) -> contiguous
    // global addresses (i0+j0+s)*512 + i0 + li  (coalesced 2B stores).
    __half* outb = g_Ddiag + (size_t)b * (NDIAG * MM);
    int warp = tid >> 5, lane = tid & 31;
    for (int s = warp; s < 127; s += 8) {
        int lo = (s > 63) ? (s - 63) : 0;
        int hi = (s < 63) ? s : 63;
        __half* rp = outb + (unsigned)(i0 + j0 + s) * 512u + (unsigned)i0;
        for (int li = lo + lane; li <= hi; li += 32)
            rp[li] = __float2half_rn(Cs[li][s - li]);
    }
}

// ---------------------------------------------------------------------------
// Kernel 2: soft-DTW, barrier-free warp-pipelined wavefront.
// One CTA per batch, 128 threads, 4 rows/thread in registers. Depth-8
// register prefetch ring for D (hides DRAM latency). Cross-warp boundary
// value flows through full-length smem array (volatile store / poll).
// ---------------------------------------------------------------------------
__device__ __forceinline__ float cellv(float dg, float up, float lf,
                                       float D, int j)
{
    // softmin_gamma(dg, up, lf): sort3, exp(0)=1 -> 2x ex2 + 1x lg2
    float mn1 = fminf(dg, up), mx1 = fmaxf(dg, up);
    float m   = fminf(mn1, lf);
    float mid = fmaxf(fminf(mx1, lf), mn1);
    float mx  = fmaxf(mx1, lf);
    float mc  = m * SCALE_EX2;
    float e1  = ex2f(fmaf(mid, -SCALE_EX2, mc));
    float e2  = ex2f(fmaf(mx,  -SCALE_EX2, mc));
    float sum = 1.0f + e1 + e2;
    float r   = fmaf(-GLN2, lg2f(sum), m) + D;
    return ((unsigned)j <= (unsigned)(NN - 1)) ? r : BIGF;
}

__global__ __launch_bounds__(128) void dtw_kernel()
{
    __shared__ unsigned sm_bound[3][NDIAG];   // boundary c3 of warps 0..2

    int b = blockIdx.x;
    int t = threadIdx.x;
    int w = t >> 5, lane = t & 31;

    for (int e = t; e < 3 * NDIAG; e += 128)
        ((unsigned*)sm_bound)[e] = POISON;
    __syncthreads();   // only barrier in the kernel

    const __half* Db = g_Ddiag + (size_t)b * (NDIAG * MM) + 4 * t;
    const int i0   = 4 * t;
    const int wlo  = w * 128;
    const int whi  = wlo + 638;          // 639 active steps per warp
    const int pwhi = wlo + 510;          // producer warp's last diagonal (w>0)

    float p1_0 = BIGF, p1_1 = BIGF, p1_2 = BIGF, p1_3 = BIGF;  // d-1 row
    float p2_0 = BIGF, p2_1 = BIGF, p2_2 = BIGF;               // d-2 row
    float nb2 = (t == 0) ? 0.0f : BIGF;   // neighbor c3 @ d-2 (C(-1,-1)=0 seed)

    // Depth-8 prefetch ring (uint2 = 4 halves = this thread's 4 rows)
    uint2 pf[8];
    #pragma unroll
    for (int j = 0; j < 8; j++)
        pf[j] = *(const uint2*)(Db + (unsigned)(wlo + j) * 512u);

    volatile unsigned* prod = (w > 0) ? &sm_bound[w - 1][0] : 0;

    for (int blk = 0; blk < 80; blk++) {
        int dbase = wlo + blk * 8;
        #pragma unroll
        for (int j = 0; j < 8; j++) {
            int d = dbase + j;
            if (d > whi) break;          // warp-uniform tail guard

            float nb1 = __shfl_up_sync(0xffffffffu, p1_3, 1);
            if (lane == 0) {
                if (w == 0 || d - 1 > pwhi) {
                    nb1 = BIGF;
                } else {
                    unsigned v = prod[d - 1];
                    while (v == POISON) v = prod[d - 1];  // producer ~128 ahead
                    nb1 = __uint_as_float(v);
                }
            }

            float2 dlo = __half22float2(*(const __half2*)&pf[j].x);
            float2 dhi = __half22float2(*(const __half2*)&pf[j].y);

            float c0 = cellv(nb2,  nb1,  p1_0, dlo.x, d - i0);
            float c1 = cellv(p2_0, p1_0, p1_1, dlo.y, d - i0 - 1);
            float c2 = cellv(p2_1, p1_1, p1_2, dhi.x, d - i0 - 2);
            float c3 = cellv(p2_2, p1_2, p1_3, dhi.y, d - i0 - 3);

            if (w < 3 && lane == 31)
                ((volatile unsigned*)&sm_bound[w][d])[0] = __float_as_uint(c3);

            nb2 = nb1;
            p2_0 = p1_0; p2_1 = p1_1; p2_2 = p1_2;
            p1_0 = c0;   p1_1 = c1;   p1_2 = c2;   p1_3 = c3;

            int dn = d + 8;
            if (dn <= whi)
                pf[j] = *(const uint2*)(Db + (unsigned)dn * 512u);
        }
    }

    if (t == 127) g_perbatch[b] = p1_3;   // C(511,511)
}

// ---------------------------------------------------------------------------
// Kernel 3: deterministic mean over batches.
// ---------------------------------------------------------------------------
__global__ void reduce_kernel(float* __restrict__ out)
{
    __shared__ float s[BATCH];
    s[threadIdx.x] = g_perbatch[threadIdx.x];
    __syncthreads();
    if (threadIdx.x == 0) {
        float acc = 0.0f;
        for (int i = 0; i < BATCH; i++) acc += s[i];
        out[0] = acc * (1.0f / BATCH);
    }
}

extern "C" void kernel_launch(void* const* d_in, const int* in_sizes, int n_in,
                              void* d_out, int out_size)
{
    const float* x = (const float*)d_in[0];
    const float* y = (const float*)d_in[1];
    float* out = (float*)d_out;

    dim3 g1(NN / 64, MM / 64, BATCH);
    pairwise_diag_kernel<<<g1, 256>>>(x, y);
    dtw_kernel<<<BATCH, 128>>>();
    reduce_kernel<<<1, BATCH>>>(out);
}